// round 6
// baseline (speedup 1.0000x reference)
#include <cuda_runtime.h>
#include <stdint.h>

// Scratch: __device__ globals (no allocation allowed).
// Invariant: g_counts is all-zero at entry to kernel_launch (zero static init,
// then re-zeroed by k_penalty_scale after each use). g_ticket likewise.
#define MAX_N 131072
#define MAX_BLOCKS 2048
__device__ int          g_counts[MAX_N];
__device__ float        g_partials[MAX_BLOCKS];
__device__ unsigned int g_ticket;

// Valence table: default 4; {1:1, 6:4, 7:3, 8:2, 9:1, 15:5, 16:6, 17:7}
__device__ __forceinline__ float valence_of(int z) {
    switch (z) {
        case 1:  return 1.0f;
        case 9:  return 1.0f;
        case 7:  return 3.0f;
        case 8:  return 2.0f;
        case 15: return 5.0f;
        case 16: return 6.0f;
        case 17: return 7.0f;
        default: return 4.0f;   // covers 6 and all others
    }
}

// K1: scatter-add bond counts from edge sources (int32 indices).
// One int4 (4 edges) per thread; atomicAdd without return compiles to RED.
// __ldcs keeps the 12.8 MB index stream from evicting hot g_counts L2 lines.
__global__ void k_count_edges(const int* __restrict__ row, int nquads, int E) {
    int stride = gridDim.x * blockDim.x;
    for (int i = blockIdx.x * blockDim.x + threadIdx.x; i < nquads; i += stride) {
        int4 e = __ldcs(reinterpret_cast<const int4*>(row) + i);
        atomicAdd(&g_counts[e.x], 1);
        atomicAdd(&g_counts[e.y], 1);
        atomicAdd(&g_counts[e.z], 1);
        atomicAdd(&g_counts[e.w], 1);
    }
    // tail: E % 4 edges
    if (blockIdx.x == 0 && threadIdx.x < (E & 3)) {
        atomicAdd(&g_counts[row[nquads * 4 + threadIdx.x]], 1);
    }
}

// K2 (fused): warp-per-row penalty compute + feature scale + loss reduce.
// Dominant pass (~205 MB read+write), streaming cache hints (h/out touched once).
// Also self-cleans g_counts for the next graph replay, and finishes the loss
// with a fence+ticket last-block reduction (no pre-zeroed loss slot needed).
__global__ void k_penalty_scale(const float4* __restrict__ h, float4* __restrict__ out,
                                const int* __restrict__ types,
                                int n_rows, int d4, float loss_scale,
                                float* loss_slot) {
    __shared__ float s_part[32];
    __shared__ bool  s_is_last;
    const int lane  = threadIdx.x & 31;
    const int warp  = threadIdx.x >> 5;
    const int gwarp = (blockIdx.x * blockDim.x + threadIdx.x) >> 5;
    const int nwarp = (gridDim.x * blockDim.x) >> 5;

    float acc = 0.0f;
    for (int row = gwarp; row < n_rows; row += nwarp) {
        float p = 1.0f;
        if (lane == 0) {
            float viol = fmaxf((float)g_counts[row] - valence_of(types[row]), 0.0f);
            g_counts[row] = 0;   // reset for next replay (each row owned by one warp)
            acc += viol;
            p = (viol > 0.0f) ? (1.0f - 0.1f * viol) : 1.0f;
        }
        p = __shfl_sync(0xFFFFFFFFu, p, 0);

        const float4* hrow = h   + (size_t)row * d4;
        float4*       orow = out + (size_t)row * d4;
        if (d4 == 64) {
            // D=256 fast path: 2 independent 16B loads before stores (MLP=2).
            float4 a = __ldcs(hrow + lane);
            float4 b = __ldcs(hrow + lane + 32);
            a.x *= p; a.y *= p; a.z *= p; a.w *= p;
            b.x *= p; b.y *= p; b.z *= p; b.w *= p;
            __stcs(orow + lane, a);
            __stcs(orow + lane + 32, b);
        } else {
            for (int c = lane; c < d4; c += 32) {
                float4 v = __ldcs(hrow + c);
                v.x *= p; v.y *= p; v.z *= p; v.w *= p;
                __stcs(orow + c, v);
            }
        }
    }

    // Block reduce: acc lives only in lane 0 of each warp.
    if (lane == 0) s_part[warp] = acc;
    __syncthreads();
    if (threadIdx.x == 0) {
        float s = 0.0f;
        int nw = blockDim.x >> 5;
        for (int w = 0; w < nw; w++) s += s_part[w];
        g_partials[blockIdx.x] = s;
        __threadfence();
        unsigned t = atomicAdd(&g_ticket, 1u);
        s_is_last = (t == gridDim.x - 1);
    }
    __syncthreads();

    // Last block to finish reduces all partials and writes the loss.
    if (s_is_last) {
        float s = 0.0f;
        for (int i = threadIdx.x; i < gridDim.x; i += blockDim.x)
            s += g_partials[i];
        #pragma unroll
        for (int off = 16; off > 0; off >>= 1)
            s += __shfl_down_sync(0xFFFFFFFFu, s, off);
        if (lane == 0) s_part[warp] = s;
        __syncthreads();
        if (threadIdx.x == 0) {
            float tot = 0.0f;
            int nw = blockDim.x >> 5;
            for (int w = 0; w < nw; w++) tot += s_part[w];
            *loss_slot = tot * loss_scale;
            g_ticket = 0;   // reset for next replay
        }
    }
}

extern "C" void kernel_launch(void* const* d_in, const int* in_sizes, int n_in,
                              void* d_out, int out_size) {
    const float* h     = (const float*)d_in[0];
    const int*   edges = (const int*)d_in[1];   // [2, E] int32; row = edges[0..E)
    const int*   types = (const int*)d_in[2];   // [N] int32
    float* out = (float*)d_out;

    const int N = in_sizes[2];
    const int E = in_sizes[1] / 2;
    const int D = in_sizes[0] / N;

    float* loss_slot = out + (out_size - 1);

    // K1: edge scatter (4 int32 indices per int4)
    {
        int nquads = E / 4;
        int threads = 256;
        int blocks = (nquads + threads - 1) / threads;
        if (blocks < 1) blocks = 1;
        if (blocks > 8192) blocks = 8192;
        k_count_edges<<<blocks, threads>>>(edges, nquads, E);
    }
    // K2: fused penalty + loss + scale (+ scratch self-clean)
    {
        float loss_scale = 0.05f / (float)N;
        int d4 = D / 4;
        int threads = 256;
        // 8 warps/block; ~full occupancy over 148 SMs, grid-stride over rows.
        int blocks = 148 * 8;
        int need = (N + 7) / 8;          // one row per warp minimum
        if (blocks > need) blocks = need;
        if (blocks < 1) blocks = 1;
        if (blocks > MAX_BLOCKS) blocks = MAX_BLOCKS;
        k_penalty_scale<<<blocks, threads>>>((const float4*)h, (float4*)out,
                                             types, N, d4, loss_scale, loss_slot);
    }
}

// round 9
// speedup vs baseline: 1.0201x; 1.0201x over previous
#include <cuda_runtime.h>
#include <stdint.h>

// Scratch: __device__ globals (no allocation allowed).
// Invariant: g_counts all-zero at entry (zero static init; re-zeroed by
// k_penalty_scale after each use -> graph-replay deterministic).
#define MAX_N 131072
__device__ int g_counts[MAX_N];

// Valence table: default 4; {1:1, 6:4, 7:3, 8:2, 9:1, 15:5, 16:6, 17:7}
__device__ __forceinline__ float valence_of(int z) {
    switch (z) {
        case 1:  return 1.0f;
        case 9:  return 1.0f;
        case 7:  return 3.0f;
        case 8:  return 2.0f;
        case 15: return 5.0f;
        case 16: return 6.0f;
        case 17: return 7.0f;
        default: return 4.0f;   // covers 6 and all others
    }
}

// K1: scatter-add bond counts (int32 indices). One int4 = 4 edges per thread.
// atomicAdd without return compiles to RED (fire-and-forget).
// Thread 0 also zeroes the loss slot so K2 can RED into it directly.
__global__ void k_count_edges(const int* __restrict__ row, int nquads, int E,
                              float* loss_slot) {
    if (blockIdx.x == 0 && threadIdx.x == 0) *loss_slot = 0.0f;
    int stride = gridDim.x * blockDim.x;
    for (int i = blockIdx.x * blockDim.x + threadIdx.x; i < nquads; i += stride) {
        int4 e = __ldcs(reinterpret_cast<const int4*>(row) + i);
        atomicAdd(&g_counts[e.x], 1);
        atomicAdd(&g_counts[e.y], 1);
        atomicAdd(&g_counts[e.z], 1);
        atomicAdd(&g_counts[e.w], 1);
    }
    // tail: E % 4 edges (gather the atom index from row[]!)
    if (blockIdx.x == 0 && threadIdx.x < (E & 3)) {
        atomicAdd(&g_counts[row[nquads * 4 + threadIdx.x]], 1);
    }
}

// K2: flat element-parallel scale pass (one float4 per thread, grid covers all).
// Penalty computed inline per thread: g_counts/types loads are L2-resident and
// broadcast-coalesced (16 threads share a row), independent of the h load ->
// full MLP, matching the 30.6us/65.8%-DRAM R3 shape. Per-row lead thread
// contributes viol to smem; one global RED per block into loss_slot.
// SELF_CLEAN path (d4 divides blockDim): rows are block-local, so after
// __syncthreads() the lead thread safely resets g_counts[row].
__global__ void k_penalty_scale(const float4* __restrict__ h, float4* __restrict__ out,
                                const int* __restrict__ types,
                                int total4, int d4, int shift, float loss_scale,
                                float* loss_slot, int self_clean) {
    __shared__ float s_loss;
    if (threadIdx.x == 0) s_loss = 0.0f;
    __syncthreads();

    int idx = blockIdx.x * blockDim.x + threadIdx.x;
    int row = 0, rem = 0;
    float viol = 0.0f;
    if (idx < total4) {
        row = (shift >= 0) ? (idx >> shift) : (idx / d4);
        rem = idx - row * d4;
        float cnt = (float)g_counts[row];              // L2 hit, broadcast
        viol = fmaxf(cnt - valence_of(types[row]), 0.0f);
        float p = (viol > 0.0f) ? (1.0f - 0.1f * viol) : 1.0f;
        float4 v = h[idx];
        v.x *= p; v.y *= p; v.z *= p; v.w *= p;
        __stcs(out + idx, v);                          // write-once stream
        if (rem == 0 && viol != 0.0f) atomicAdd(&s_loss, viol);
    }
    __syncthreads();   // all reads of g_counts in this block are done
    if (idx < total4 && rem == 0 && self_clean) g_counts[row] = 0;
    if (threadIdx.x == 0 && s_loss != 0.0f)
        atomicAdd(loss_slot, s_loss * loss_scale);
}

// K3 (generic fallback only): zero counts when rows span blocks.
__global__ void k_clean(int n) {
    int i = blockIdx.x * blockDim.x + threadIdx.x;
    if (i < n) g_counts[i] = 0;
}

extern "C" void kernel_launch(void* const* d_in, const int* in_sizes, int n_in,
                              void* d_out, int out_size) {
    const float* h     = (const float*)d_in[0];
    const int*   edges = (const int*)d_in[1];   // [2, E] int32; row = edges[0..E)
    const int*   types = (const int*)d_in[2];   // [N] int32
    float* out = (float*)d_out;

    const int N = in_sizes[2];
    const int E = in_sizes[1] / 2;
    const int D = in_sizes[0] / N;

    float* loss_slot = out + (out_size - 1);

    // K1: edge scatter (+ zero loss slot)
    {
        int nquads = E / 4;
        int threads = 256;
        int blocks = (nquads + threads - 1) / threads;
        if (blocks < 1) blocks = 1;
        if (blocks > 8192) blocks = 8192;
        k_count_edges<<<blocks, threads>>>(edges, nquads, E, loss_slot);
    }
    // K2: flat scale + inline penalty + loss (+ self-clean when rows are block-local)
    {
        float loss_scale = 0.05f / (float)N;
        int d4 = D / 4;
        int shift = -1;
        if (d4 > 0 && (d4 & (d4 - 1)) == 0) {
            shift = 0;
            while ((1 << shift) != d4) shift++;
        }
        int total4 = (int)((long long)N * D / 4);
        int threads = 256;
        int self_clean = (d4 > 0 && d4 <= threads && (threads % d4) == 0) ? 1 : 0;
        int blocks = (total4 + threads - 1) / threads;
        if (blocks < 1) blocks = 1;
        k_penalty_scale<<<blocks, threads>>>((const float4*)h, (float4*)out,
                                             types, total4, d4, shift,
                                             loss_scale, loss_slot, self_clean);
        if (!self_clean) {
            int cblocks = (N + 255) / 256;
            k_clean<<<cblocks, 256>>>(N);
        }
    }
}

// round 10
// speedup vs baseline: 1.1515x; 1.1288x over previous
#include <cuda_runtime.h>
#include <stdint.h>

// Scratch: __device__ globals (no allocation allowed).
// Invariant: g_counts all-zero at entry (zero static init; k_penalty resets
// each slot after reading it -> graph-replay deterministic).
#define MAX_N 131072
__device__ int   g_counts[MAX_N];
__device__ float g_penalty[MAX_N];

// Valence table: default 4; {1:1, 6:4, 7:3, 8:2, 9:1, 15:5, 16:6, 17:7}
__device__ __forceinline__ float valence_of(int z) {
    switch (z) {
        case 1:  return 1.0f;
        case 9:  return 1.0f;
        case 7:  return 3.0f;
        case 8:  return 2.0f;
        case 15: return 5.0f;
        case 16: return 6.0f;
        case 17: return 7.0f;
        default: return 4.0f;   // covers 6 and all others
    }
}

// K1: scatter-add bond counts (int32 indices). One int4 = 4 edges per thread.
// PLAIN loads (the .cs hint measured ~+7us on this stream in R9).
// atomicAdd without return compiles to RED. Thread 0 zeroes the loss slot.
__global__ void k_count_edges(const int* __restrict__ row, int nquads, int E,
                              float* loss_slot) {
    if (blockIdx.x == 0 && threadIdx.x == 0) *loss_slot = 0.0f;
    int stride = gridDim.x * blockDim.x;
    for (int i = blockIdx.x * blockDim.x + threadIdx.x; i < nquads; i += stride) {
        int4 e = reinterpret_cast<const int4*>(row)[i];
        atomicAdd(&g_counts[e.x], 1);
        atomicAdd(&g_counts[e.y], 1);
        atomicAdd(&g_counts[e.z], 1);
        atomicAdd(&g_counts[e.w], 1);
    }
    // tail: E % 4 edges (gather atom index from row[])
    if (blockIdx.x == 0 && threadIdx.x < (E & 3)) {
        atomicAdd(&g_counts[row[nquads * 4 + threadIdx.x]], 1);
    }
}

// K2: per-atom penalty precompute + loss reduce + scratch self-clean.
// Tiny kernel (N threads over 1.2 MB of L2-resident data).
__global__ void k_penalty(const int* __restrict__ types, int n,
                          float loss_scale, float* loss_slot) {
    __shared__ float s_part[32];
    int i = blockIdx.x * blockDim.x + threadIdx.x;
    float viol = 0.0f;
    if (i < n) {
        viol = fmaxf((float)g_counts[i] - valence_of(types[i]), 0.0f);
        g_counts[i] = 0;   // reset for next graph replay
        g_penalty[i] = (viol > 0.0f) ? (1.0f - 0.1f * viol) : 1.0f;
    }
    // warp reduce
    #pragma unroll
    for (int off = 16; off > 0; off >>= 1)
        viol += __shfl_down_sync(0xFFFFFFFFu, viol, off);
    int lane = threadIdx.x & 31, warp = threadIdx.x >> 5;
    if (lane == 0) s_part[warp] = viol;
    __syncthreads();
    if (threadIdx.x == 0) {
        float s = 0.0f;
        int nw = blockDim.x >> 5;
        for (int w = 0; w < nw; w++) s += s_part[w];
        if (s != 0.0f) atomicAdd(loss_slot, s * loss_scale);
    }
}

// K3: h_new = h * penalty[row]. R3-measured shape (plain LDG/STG, precomputed
// penalty), extended to 2 float4 per thread: both loads issue before both
// stores (MLP_p1=2) to push DRAM% above the 65.8% R3 baseline.
__global__ void k_scale_h(const float4* __restrict__ h, float4* __restrict__ out,
                          int total4, int pairs, int d4, int shift) {
    int i0 = blockIdx.x * blockDim.x + threadIdx.x;
    if (i0 < pairs) {
        int i1 = i0 + pairs;
        int r0 = (shift >= 0) ? (i0 >> shift) : (i0 / d4);
        float4 a = h[i0];
        float p0 = g_penalty[r0];
        if (i1 < total4) {
            int r1 = (shift >= 0) ? (i1 >> shift) : (i1 / d4);
            float4 b = h[i1];
            float p1 = g_penalty[r1];
            a.x *= p0; a.y *= p0; a.z *= p0; a.w *= p0;
            b.x *= p1; b.y *= p1; b.z *= p1; b.w *= p1;
            out[i0] = a;
            out[i1] = b;
        } else {
            a.x *= p0; a.y *= p0; a.z *= p0; a.w *= p0;
            out[i0] = a;
        }
    }
}

extern "C" void kernel_launch(void* const* d_in, const int* in_sizes, int n_in,
                              void* d_out, int out_size) {
    const float* h     = (const float*)d_in[0];
    const int*   edges = (const int*)d_in[1];   // [2, E] int32; row = edges[0..E)
    const int*   types = (const int*)d_in[2];   // [N] int32
    float* out = (float*)d_out;

    const int N = in_sizes[2];
    const int E = in_sizes[1] / 2;
    const int D = in_sizes[0] / N;

    float* loss_slot = out + (out_size - 1);

    // K1: edge scatter (+ zero loss slot)
    {
        int nquads = E / 4;
        int threads = 256;
        int blocks = (nquads + threads - 1) / threads;
        if (blocks < 1) blocks = 1;
        if (blocks > 8192) blocks = 8192;
        k_count_edges<<<blocks, threads>>>(edges, nquads, E, loss_slot);
    }
    // K2: penalty precompute + loss + counts reset
    {
        float loss_scale = 0.05f / (float)N;
        int threads = 256, blocks = (N + threads - 1) / threads;
        k_penalty<<<blocks, threads>>>(types, N, loss_scale, loss_slot);
    }
    // K3: scale features (2 float4 per thread)
    {
        int d4 = D / 4;
        int shift = -1;
        if (d4 > 0 && (d4 & (d4 - 1)) == 0) {
            shift = 0;
            while ((1 << shift) != d4) shift++;
        }
        int total4 = (int)((long long)N * D / 4);
        int pairs = (total4 + 1) / 2;
        int threads = 256;
        int blocks = (pairs + threads - 1) / threads;
        if (blocks < 1) blocks = 1;
        k_scale_h<<<blocks, threads>>>((const float4*)h, (float4*)out,
                                       total4, pairs, d4, shift);
    }
}